// round 1
// baseline (speedup 1.0000x reference)
#include <cuda_runtime.h>
#include <cuda_bf16.h>
#include <cstdint>

// Problem constants
#define Bb   16
#define Tt   256
#define Kk   128
#define DE   256
#define DK   256
#define Uu   128

// Scratch (device globals; no allocation allowed)
__device__ float g_E [Bb * Tt * Uu];   // [B,T,U]  encoder projection, 2 MB
__device__ float g_Kp[Bb * Kk * Uu];   // [B,K,U]  knowledge projection, 1 MB

// ---------------------------------------------------------------------------
// Projection: out[m, n] = sum_d X[m,d] * W[d,n] + bias[n],  n in [0,128)
// Block: 128 threads, handles 8 rows of X (staged in smem), thread = column n.
// W row loads are coalesced and L1-resident (W is 128 KB, fits L1).
// ---------------------------------------------------------------------------
__global__ void proj_kernel(const float* __restrict__ X,
                            const float* __restrict__ W,
                            const float* __restrict__ bias,
                            int which_out /* 0 -> g_E, 1 -> g_Kp */) {
    __shared__ float sX[8][DE];  // 8 KB
    const int m0  = blockIdx.x * 8;
    const int tid = threadIdx.x;           // 0..127 = output column

    // stage 8 rows of X
    #pragma unroll
    for (int i = tid; i < 8 * DE; i += 128) {
        sX[i >> 8][i & 255] = X[(size_t)m0 * DE + i];
    }
    __syncthreads();

    float acc[8];
    const float bv = bias[tid];
    #pragma unroll
    for (int r = 0; r < 8; r++) acc[r] = bv;

    #pragma unroll 4
    for (int kk = 0; kk < DE; kk++) {
        const float w = W[kk * Uu + tid];
        #pragma unroll
        for (int r = 0; r < 8; r++) acc[r] = fmaf(sX[r][kk], w, acc[r]);
    }

    float* out = which_out ? g_Kp : g_E;
    #pragma unroll
    for (int r = 0; r < 8; r++) out[(size_t)(m0 + r) * Uu + tid] = acc[r];
}

// ---------------------------------------------------------------------------
// Fused score + softmax + context kernel.
// Grid: 256 blocks = (b, 16-timestep tile). Block: 256 threads.
// Phase 1: scores  s[t,k] = sum_u tanh(E[b,t,u] + Kp[b,k,u]) * V[u] + bV
//          thread (t = tid>>4, k0 = tid&15) computes 8 k values (k0 + 16*i).
//          sKp padded to stride 129 -> conflict-free (bank = (k0+16i+u)%32).
// Phase 2: softmax over k (8 warps x 2 rows, warp shuffle reductions).
// Phase 3: context[t,d] = sum_k attn[t,k] * know[b,k,d]; thread = d, 16 accs.
// ---------------------------------------------------------------------------
#define TT 16
#define KP_STRIDE 129
#define E_STRIDE  132

__global__ __launch_bounds__(256, 2)
void attn_kernel(const float* __restrict__ know,
                 const float* __restrict__ Vv,
                 const float* __restrict__ bVp,
                 float* __restrict__ out) {
    extern __shared__ float sm[];
    float* sKp = sm;                                 // 128 * 129
    float* sE  = sKp + Kk * KP_STRIDE;               // TT * 132
    float* sS  = sE  + TT * E_STRIDE;                // TT * 128 (scores -> attn)
    float* sV  = sS  + TT * Kk;                      // 128

    const int b   = blockIdx.x >> 4;
    const int t0  = (blockIdx.x & 15) * TT;
    const int tid = threadIdx.x;

    // stage Kp[b] (64 KB logical) with padding
    const float* Kpb = g_Kp + (size_t)b * (Kk * Uu);
    for (int i = tid; i < Kk * Uu; i += 256) {
        sKp[(i >> 7) * KP_STRIDE + (i & 127)] = Kpb[i];
    }
    // stage E rows for this t-tile
    const float* Eb = g_E + (size_t)(b * Tt + t0) * Uu;
    for (int i = tid; i < TT * Uu; i += 256) {
        sE[(i >> 7) * E_STRIDE + (i & 127)] = Eb[i];
    }
    if (tid < 128) sV[tid] = Vv[tid];
    __syncthreads();

    const float bV = bVp[0];

    // ---- Phase 1: scores ----
    const int t  = tid >> 4;       // 0..15
    const int k0 = tid & 15;       // 0..15, k = k0 + 16*i
    float acc[8];
    #pragma unroll
    for (int i = 0; i < 8; i++) acc[i] = 0.0f;

    const float* eRow = sE + t * E_STRIDE;
    #pragma unroll 2
    for (int u = 0; u < Uu; u++) {
        const float eu = eRow[u];
        const float vu = sV[u];
        #pragma unroll
        for (int i = 0; i < 8; i++) {
            float x = eu + sKp[(k0 + 16 * i) * KP_STRIDE + u];
            float th;
            asm("tanh.approx.f32 %0, %1;" : "=f"(th) : "f"(x));
            acc[i] = fmaf(th, vu, acc[i]);
        }
    }
    #pragma unroll
    for (int i = 0; i < 8; i++) sS[t * Kk + k0 + 16 * i] = acc[i] + bV;
    __syncthreads();

    // ---- Phase 2: softmax over k (per t row) ----
    {
        const int wid  = tid >> 5;
        const int lane = tid & 31;
        #pragma unroll
        for (int tt = wid * 2; tt < wid * 2 + 2; tt++) {
            float* row = sS + tt * Kk;
            float m = -1e30f;
            float v0 = row[lane], v1 = row[lane + 32], v2 = row[lane + 64], v3 = row[lane + 96];
            m = fmaxf(fmaxf(v0, v1), fmaxf(v2, v3));
            #pragma unroll
            for (int o = 16; o > 0; o >>= 1) m = fmaxf(m, __shfl_xor_sync(~0u, m, o));
            float e0 = __expf(v0 - m), e1 = __expf(v1 - m), e2 = __expf(v2 - m), e3 = __expf(v3 - m);
            float s = (e0 + e1) + (e2 + e3);
            #pragma unroll
            for (int o = 16; o > 0; o >>= 1) s += __shfl_xor_sync(~0u, s, o);
            const float inv = __frcp_rn(s);
            row[lane]      = e0 * inv;
            row[lane + 32] = e1 * inv;
            row[lane + 64] = e2 * inv;
            row[lane + 96] = e3 * inv;
        }
    }
    __syncthreads();

    // ---- Phase 3: context[t, d] = sum_k attn[t,k] * know[b,k,d] ----
    const float* kb = know + (size_t)b * Kk * DK;
    float cacc[TT];
    #pragma unroll
    for (int r = 0; r < TT; r++) cacc[r] = 0.0f;

    const int d = tid;  // 0..255 = DK
    #pragma unroll 4
    for (int k = 0; k < Kk; k++) {
        const float val = __ldg(kb + (size_t)k * DK + d);
        #pragma unroll
        for (int r = 0; r < TT; r++) cacc[r] = fmaf(sS[r * Kk + k], val, cacc[r]);
    }

    float* ob = out + (size_t)(b * Tt + t0) * DK;
    #pragma unroll
    for (int r = 0; r < TT; r++) ob[(size_t)r * DK + d] = cacc[r];
}

// ---------------------------------------------------------------------------
// Launch. Inputs (metadata order):
//   0 knowledge_onehot [B,K,D_K] f32
//   1 encoder_outputs  [B,T,D_E] f32
//   2 W1 [D_E,U]  3 b1 [U]  4 W2 [D_K,U]  5 b2 [U]  6 V [U,1]  7 bV [1]
// Output: context [B,T,D_K] f32
// ---------------------------------------------------------------------------
extern "C" void kernel_launch(void* const* d_in, const int* in_sizes, int n_in,
                              void* d_out, int out_size) {
    const float* know = (const float*)d_in[0];
    const float* enc  = (const float*)d_in[1];
    const float* W1   = (const float*)d_in[2];
    const float* b1   = (const float*)d_in[3];
    const float* W2   = (const float*)d_in[4];
    const float* b2   = (const float*)d_in[5];
    const float* V    = (const float*)d_in[6];
    const float* bV   = (const float*)d_in[7];
    float* out = (float*)d_out;

    const int attn_smem = (Kk * KP_STRIDE + TT * E_STRIDE + TT * Kk + 128) * (int)sizeof(float);
    cudaFuncSetAttribute(attn_kernel, cudaFuncAttributeMaxDynamicSharedMemorySize, attn_smem);

    // E projection: M = B*T = 4096 rows -> 512 blocks
    proj_kernel<<<(Bb * Tt) / 8, 128>>>(enc, W1, b1, /*which_out=*/0);
    // Kp projection: M = B*K = 2048 rows -> 256 blocks
    proj_kernel<<<(Bb * Kk) / 8, 128>>>(know, W2, b2, /*which_out=*/1);
    // fused attention: 16 b * 16 t-tiles = 256 blocks
    attn_kernel<<<Bb * (Tt / TT), 256, attn_smem>>>(know, V, bV, out);
}